// round 13
// baseline (speedup 1.0000x reference)
#include <cuda_runtime.h>
#include <cuda_bf16.h>

#define NUM_G 32768

// Scratch (allocation-free __device__ globals; zero-initialized at load).
// INVARIANT: all scratch is zero at kernel_launch entry; k_fin restores
// everything to zero, so every graph replay sees identical state.
__device__ float4   g_acc[NUM_G];   // {tsum, psum, S = sum exp(t)*p, count}
__device__ float    g_total;
__device__ int      g_nvalid;
__device__ unsigned g_done;

// Pure-FMA exp: exp(x) = 2^(x*log2e). Magic-number round, deg-5 poly on [-0.5,0.5].
__device__ __forceinline__ float fexp(float x) {
    const float L2E = 1.4426950408889634f;
    float z  = fmaf(x, L2E, 12582912.0f);
    int   n  = __float_as_int(z) - 0x4B400000;
    float zi = z - 12582912.0f;
    float f  = fmaf(x, L2E, -zi);
    float p  = 1.3333558146e-3f;
    p = fmaf(p, f, 9.6181291076e-3f);
    p = fmaf(p, f, 5.5504108664e-2f);
    p = fmaf(p, f, 2.4022650696e-1f);
    p = fmaf(p, f, 6.9314718056e-1f);
    p = fmaf(p, f, 1.0f);
    return __int_as_float(__float_as_int(p) + (n << 23));
}

// One 16-byte vectorized L2 reduction: {tsum += te, psum += pe, S += te*p, count += 1}
__device__ __forceinline__ void red4(float4* a, float te, float pe, float s) {
    asm volatile("red.global.add.v4.f32 [%0], {%1, %2, %3, %4};"
                 :: "l"(a), "f"(te), "f"(pe), "f"(s), "f"(1.0f) : "memory");
}

// Streaming float4 / int4 loads (evict-first).
__device__ __forceinline__ float4 ldcs4(const float4* p) {
    float4 v;
    asm volatile("ld.global.cs.v4.f32 {%0,%1,%2,%3}, [%4];"
                 : "=f"(v.x), "=f"(v.y), "=f"(v.z), "=f"(v.w) : "l"(p));
    return v;
}
__device__ __forceinline__ int4 ldcs4i(const int4* p) {
    int4 v;
    asm volatile("ld.global.cs.v4.b32 {%0,%1,%2,%3}, [%4];"
                 : "=r"(v.x), "=r"(v.y), "=r"(v.z), "=r"(v.w) : "l"(p));
    return v;
}

// Empty kernel: pads launch positions so the ncu capture slot (launch index 3)
// lands on k_accum. Near-free under graph replay.
__global__ void k_dummy() {}

// One float4 chunk: 3 loads, 4 fexp, 4 red4. Kept small so register liveness
// stays low across the two sequential calls (occupancy is the binding limit).
__device__ __forceinline__ void accum_chunk(const float4* __restrict__ p4,
                                            const float4* __restrict__ t4,
                                            const int4*  __restrict__ g4, int i) {
    float4 p = ldcs4(&p4[i]);
    float4 t = ldcs4(&t4[i]);
    int4   g = ldcs4i(&g4[i]);
    float ex = fexp(t.x), ey = fexp(t.y), ez = fexp(t.z), ew = fexp(t.w);
    red4(&g_acc[g.x], ex, fexp(p.x), ex * p.x);
    red4(&g_acc[g.y], ey, fexp(p.y), ey * p.y);
    red4(&g_acc[g.z], ez, fexp(p.z), ez * p.z);
    red4(&g_acc[g.w], ew, fexp(p.w), ew * p.w);
}

// Pass 1: per-group sums of exp(t), exp(p), exp(t)*p, count — ONE red.v4 per
// element. Two SEQUENTIAL chunks per thread (low reg pressure) + occupancy 8
// blocks/SM: doubles resident warps vs R12 (occ 50% -> ~100%) to saturate the
// L2 atomic pipe (was 61%).
__global__ void __launch_bounds__(256, 8) k_accum(const float4* __restrict__ p4,
                                                  const float4* __restrict__ t4,
                                                  const int4*  __restrict__ g4, int nv) {
    int half = nv >> 1;
    int i = blockIdx.x * blockDim.x + threadIdx.x;
    if (i >= half) return;
    accum_chunk(p4, t4, g4, i);
    accum_chunk(p4, t4, g4, i + half);
}

// Pass 2 (PDL secondary): per-group loss_g = log(psum) - S/tsum (0 when count<2),
// global reduce, output write, scratch reset.
__global__ void k_fin(float* __restrict__ out) {
    asm volatile("griddepcontrol.wait;" ::: "memory");

    int base = blockIdx.x * 512 + threadIdx.x;
    float4 a0 = __ldcg(&g_acc[base]);
    float4 a1 = __ldcg(&g_acc[base + 256]);
    g_acc[base]       = make_float4(0.f, 0.f, 0.f, 0.f);
    g_acc[base + 256] = make_float4(0.f, 0.f, 0.f, 0.f);

    bool v0 = (a0.w >= 1.5f), v1 = (a1.w >= 1.5f);
    float s = 0.0f;
    if (v0) s  = logf(a0.y) - a0.z / a0.x;
    if (v1) s += logf(a1.y) - a1.z / a1.x;
    int c = (int)v0 + (int)v1;

    #pragma unroll
    for (int o = 16; o > 0; o >>= 1) {
        s += __shfl_down_sync(0xffffffffu, s, o);
        c += __shfl_down_sync(0xffffffffu, c, o);
    }
    __shared__ float sh[8];
    __shared__ int   shc[8];
    int lane = threadIdx.x & 31, wid = threadIdx.x >> 5;
    if (lane == 0) { sh[wid] = s; shc[wid] = c; }
    __syncthreads();
    if (wid == 0) {
        s = (lane < 8) ? sh[lane] : 0.0f;
        c = (lane < 8) ? shc[lane] : 0;
        #pragma unroll
        for (int o = 4; o > 0; o >>= 1) {
            s += __shfl_down_sync(0xffffffffu, s, o);
            c += __shfl_down_sync(0xffffffffu, c, o);
        }
        if (lane == 0) {
            atomicAdd(&g_total, s);
            atomicAdd(&g_nvalid, c);
            __threadfence();
            unsigned t = atomicAdd(&g_done, 1u);
            if (t == gridDim.x - 1) {
                int   nvg = *(volatile int*)&g_nvalid;
                float tt  = *(volatile float*)&g_total;
                out[0] = (nvg > 0) ? (tt / (float)nvg) : 0.0f;
                g_total = 0.0f; g_nvalid = 0; g_done = 0u;
            }
        }
    }
}

extern "C" void kernel_launch(void* const* d_in, const int* in_sizes, int n_in,
                              void* d_out, int out_size) {
    const float* pred = (const float*)d_in[0];
    const float* targ = (const float*)d_in[1];
    const int*   gid  = (const int*)d_in[2];
    float* out = (float*)d_out;
    int n  = in_sizes[0];
    int nv = n / 4;                       // n is a multiple of 4 (4,194,304)
    int gb = (nv / 2 + 255) / 256;        // 2048 blocks, 8 elements/thread

    k_dummy<<<1, 32>>>();                 // pos 0 (capture-slot padding)
    k_dummy<<<1, 32>>>();                 // pos 1
    k_dummy<<<1, 32>>>();                 // pos 2

    k_accum<<<gb, 256>>>((const float4*)pred, (const float4*)targ,
                         (const int4*)gid, nv);   // pos 3 -> ncu capture slot

    cudaLaunchConfig_t cfg = {};
    cfg.gridDim  = dim3(64);
    cfg.blockDim = dim3(256);
    cfg.stream   = 0;
    cudaLaunchAttribute attr[1];
    attr[0].id = cudaLaunchAttributeProgrammaticStreamSerialization;
    attr[0].val.programmaticStreamSerializationAllowed = 1;
    cfg.attrs    = attr;
    cfg.numAttrs = 1;
    cudaLaunchKernelEx(&cfg, k_fin, out); // pos 4
}

// round 14
// speedup vs baseline: 1.1549x; 1.1549x over previous
#include <cuda_runtime.h>
#include <cuda_bf16.h>

#define NUM_G 32768
#define NREP  4      // accumulator replicas (cuts per-address red serialization 4x)

// Scratch (allocation-free __device__ globals; zero-initialized at load).
// INVARIANT: all scratch is zero at kernel_launch entry; k_fin restores
// everything to zero, so every graph replay sees identical state.
__device__ float4   g_acc[NREP * NUM_G];  // {tsum, psum, S = sum exp(t)*p, count}
__device__ float    g_total;
__device__ int      g_nvalid;
__device__ unsigned g_done;

// Pure-FMA exp: exp(x) = 2^(x*log2e). Magic-number round, deg-5 poly on [-0.5,0.5].
__device__ __forceinline__ float fexp(float x) {
    const float L2E = 1.4426950408889634f;
    float z  = fmaf(x, L2E, 12582912.0f);
    int   n  = __float_as_int(z) - 0x4B400000;
    float zi = z - 12582912.0f;
    float f  = fmaf(x, L2E, -zi);
    float p  = 1.3333558146e-3f;
    p = fmaf(p, f, 9.6181291076e-3f);
    p = fmaf(p, f, 5.5504108664e-2f);
    p = fmaf(p, f, 2.4022650696e-1f);
    p = fmaf(p, f, 6.9314718056e-1f);
    p = fmaf(p, f, 1.0f);
    return __int_as_float(__float_as_int(p) + (n << 23));
}

// One 16-byte vectorized L2 reduction: {tsum += te, psum += pe, S += te*p, count += 1}
__device__ __forceinline__ void red4(float4* a, float te, float pe, float s) {
    asm volatile("red.global.add.v4.f32 [%0], {%1, %2, %3, %4};"
                 :: "l"(a), "f"(te), "f"(pe), "f"(s), "f"(1.0f) : "memory");
}

// Streaming float4 / int4 loads (evict-first).
__device__ __forceinline__ float4 ldcs4(const float4* p) {
    float4 v;
    asm volatile("ld.global.cs.v4.f32 {%0,%1,%2,%3}, [%4];"
                 : "=f"(v.x), "=f"(v.y), "=f"(v.z), "=f"(v.w) : "l"(p));
    return v;
}
__device__ __forceinline__ int4 ldcs4i(const int4* p) {
    int4 v;
    asm volatile("ld.global.cs.v4.b32 {%0,%1,%2,%3}, [%4];"
                 : "=r"(v.x), "=r"(v.y), "=r"(v.z), "=r"(v.w) : "l"(p));
    return v;
}

// One float4 chunk: 3 loads, 4 fexp, 4 red4 into this block's replica.
__device__ __forceinline__ void accum_chunk(const float4* __restrict__ p4,
                                            const float4* __restrict__ t4,
                                            const int4*  __restrict__ g4,
                                            float4* __restrict__ acc, int i) {
    float4 p = ldcs4(&p4[i]);
    float4 t = ldcs4(&t4[i]);
    int4   g = ldcs4i(&g4[i]);
    float ex = fexp(t.x), ey = fexp(t.y), ez = fexp(t.z), ew = fexp(t.w);
    red4(&acc[g.x], ex, fexp(p.x), ex * p.x);
    red4(&acc[g.y], ey, fexp(p.y), ey * p.y);
    red4(&acc[g.z], ez, fexp(p.z), ez * p.z);
    red4(&acc[g.w], ew, fexp(p.w), ew * p.w);
}

// Pass 1: per-group sums of exp(t), exp(p), exp(t)*p, count — ONE red.v4 per
// element, into one of NREP replicas (by blockIdx) to cut same-address
// serialization at the LTS atomic ALU.
__global__ void __launch_bounds__(256, 8) k_accum(const float4* __restrict__ p4,
                                                  const float4* __restrict__ t4,
                                                  const int4*  __restrict__ g4, int nv) {
    int half = nv >> 1;
    int i = blockIdx.x * blockDim.x + threadIdx.x;
    if (i >= half) return;
    float4* acc = g_acc + ((blockIdx.x & (NREP - 1)) << 15);   // replica base
    accum_chunk(p4, t4, g4, acc, i);
    accum_chunk(p4, t4, g4, acc, i + half);
}

// Pass 2 (PDL secondary): merge replicas, per-group loss_g = log(psum) - S/tsum
// (0 when count<2), global reduce, output write, scratch reset.
// 64 blocks x 256 threads = 2 groups/thread.
__global__ void k_fin(float* __restrict__ out) {
    asm volatile("griddepcontrol.wait;" ::: "memory");

    int base = blockIdx.x * 512 + threadIdx.x;       // groups: base, base+256
    const float4 Z = make_float4(0.f, 0.f, 0.f, 0.f);
    float4 a0 = Z, a1 = Z;
    #pragma unroll
    for (int r = 0; r < NREP; r++) {
        float4 u = __ldcg(&g_acc[r * NUM_G + base]);
        float4 v = __ldcg(&g_acc[r * NUM_G + base + 256]);
        a0.x += u.x; a0.y += u.y; a0.z += u.z; a0.w += u.w;
        a1.x += v.x; a1.y += v.y; a1.z += v.z; a1.w += v.w;
        g_acc[r * NUM_G + base]       = Z;           // reset for next replay
        g_acc[r * NUM_G + base + 256] = Z;
    }

    bool v0 = (a0.w >= 1.5f), v1 = (a1.w >= 1.5f);   // count >= 2
    float s = 0.0f;
    if (v0) s  = logf(a0.y) - a0.z / a0.x;
    if (v1) s += logf(a1.y) - a1.z / a1.x;
    int c = (int)v0 + (int)v1;

    #pragma unroll
    for (int o = 16; o > 0; o >>= 1) {
        s += __shfl_down_sync(0xffffffffu, s, o);
        c += __shfl_down_sync(0xffffffffu, c, o);
    }
    __shared__ float sh[8];
    __shared__ int   shc[8];
    int lane = threadIdx.x & 31, wid = threadIdx.x >> 5;
    if (lane == 0) { sh[wid] = s; shc[wid] = c; }
    __syncthreads();
    if (wid == 0) {
        s = (lane < 8) ? sh[lane] : 0.0f;
        c = (lane < 8) ? shc[lane] : 0;
        #pragma unroll
        for (int o = 4; o > 0; o >>= 1) {
            s += __shfl_down_sync(0xffffffffu, s, o);
            c += __shfl_down_sync(0xffffffffu, c, o);
        }
        if (lane == 0) {
            atomicAdd(&g_total, s);
            atomicAdd(&g_nvalid, c);
            __threadfence();
            unsigned t = atomicAdd(&g_done, 1u);
            if (t == gridDim.x - 1) {
                int   nvg = *(volatile int*)&g_nvalid;
                float tt  = *(volatile float*)&g_total;
                out[0] = (nvg > 0) ? (tt / (float)nvg) : 0.0f;
                g_total = 0.0f; g_nvalid = 0; g_done = 0u;
            }
        }
    }
}

extern "C" void kernel_launch(void* const* d_in, const int* in_sizes, int n_in,
                              void* d_out, int out_size) {
    const float* pred = (const float*)d_in[0];
    const float* targ = (const float*)d_in[1];
    const int*   gid  = (const int*)d_in[2];
    float* out = (float*)d_out;
    int n  = in_sizes[0];
    int nv = n / 4;                       // n is a multiple of 4 (4,194,304)
    int gb = (nv / 2 + 255) / 256;        // 2048 blocks, 8 elements/thread

    k_accum<<<gb, 256>>>((const float4*)pred, (const float4*)targ,
                         (const int4*)gid, nv);

    cudaLaunchConfig_t cfg = {};
    cfg.gridDim  = dim3(64);
    cfg.blockDim = dim3(256);
    cfg.stream   = 0;
    cudaLaunchAttribute attr[1];
    attr[0].id = cudaLaunchAttributeProgrammaticStreamSerialization;
    attr[0].val.programmaticStreamSerializationAllowed = 1;
    cfg.attrs    = attr;
    cfg.numAttrs = 1;
    cudaLaunchKernelEx(&cfg, k_fin, out);
}